// round 16
// baseline (speedup 1.0000x reference)
#include <cuda_runtime.h>
#include <cuda_bf16.h>
#include <math.h>
#include <stdint.h>

#define TSEQ   2048
#define NTOK   8192
#define DM     1024
#define DH     128
#define QSCALE 0.03125f                 // 1/sqrt(1024)
#define LOG2E  1.4426950408889634f

// bf16 hi/lo planes of inputs (pre-converted once per launch)
__device__ unsigned short g_Xhi[NTOK * DM], g_Xlo[NTOK * DM];
__device__ unsigned short g_Whi[3 * DH * DM], g_Wlo[3 * DH * DM];
// Q,K token-major bf16 hi/lo planes; Vt transposed [DH][NTOK] planes.
__device__ unsigned short g_Qhi[NTOK * DH], g_Qlo[NTOK * DH];
__device__ unsigned short g_Khi[NTOK * DH], g_Klo[NTOK * DH];
__device__ unsigned short g_Vthi[DH * NTOK], g_Vtlo[DH * NTOK];
__device__ float g_ctab[TSEQ * DH];
__device__ float g_stab[TSEQ * DH];
// split-K partials: [b][qt32][chunk8][64 q][128 d]; m/l in log2 units
__device__ float g_Op[4 * 32 * 8 * 64 * DH];
__device__ float g_m [4 * 32 * 8 * 64];
__device__ float g_l [4 * 32 * 8 * 64];

__device__ __forceinline__ float ex2f(float x) {
    float y; asm("ex2.approx.ftz.f32 %0, %1;" : "=f"(y) : "f"(x)); return y;
}
__device__ __forceinline__ uint32_t s2u(const void* p) {
    uint32_t a;
    asm("{ .reg .u64 t; cvta.to.shared.u64 t, %1; cvt.u32.u64 %0, t; }"
        : "=r"(a) : "l"(p));
    return a;
}
#define CPA16(dst, src) \
    asm volatile("cp.async.cg.shared.global [%0], [%1], 16;" :: "r"(dst), "l"(src) : "memory")
#define CPA_COMMIT() asm volatile("cp.async.commit_group;" ::: "memory")
#define CPA_WAIT0()  asm volatile("cp.async.wait_group 0;" ::: "memory")
#define CPA_WAIT1()  asm volatile("cp.async.wait_group 1;" ::: "memory")

#define LDSM4(r0, r1, r2, r3, addr) \
    asm volatile("ldmatrix.sync.aligned.m8n8.x4.shared.b16 {%0,%1,%2,%3}, [%4];" \
        : "=r"(r0), "=r"(r1), "=r"(r2), "=r"(r3) : "r"(addr))

// bf16 m16n8k16 HMMA
__device__ __forceinline__ void mma16(float* c, const uint32_t* a, const uint32_t* b) {
    asm volatile(
        "mma.sync.aligned.m16n8k16.row.col.f32.bf16.bf16.f32 "
        "{%0,%1,%2,%3}, {%4,%5,%6,%7}, {%8,%9}, {%0,%1,%2,%3};"
        : "+f"(c[0]), "+f"(c[1]), "+f"(c[2]), "+f"(c[3])
        : "r"(a[0]), "r"(a[1]), "r"(a[2]), "r"(a[3]), "r"(b[0]), "r"(b[1]));
}

__device__ __forceinline__ void split2(float f0, float f1, uint32_t& hi, uint32_t& lo) {
    __nv_bfloat16 h0 = __float2bfloat16(f0);
    __nv_bfloat16 h1 = __float2bfloat16(f1);
    __nv_bfloat16 l0 = __float2bfloat16(f0 - __bfloat162float(h0));
    __nv_bfloat16 l1 = __float2bfloat16(f1 - __bfloat162float(h1));
    hi = (uint32_t)__bfloat16_as_ushort(h0) | ((uint32_t)__bfloat16_as_ushort(h1) << 16);
    lo = (uint32_t)__bfloat16_as_ushort(l0) | ((uint32_t)__bfloat16_as_ushort(l1) << 16);
}

// ---------------------------------------------------------------------------
__global__ __launch_bounds__(128) void rope_table(const float* __restrict__ theta) {
    int p = blockIdx.x, n = threadIdx.x;
    float s, c;
    sincosf((float)(p + 1) * theta[n], &s, &c);
    g_ctab[p * DH + n] = c;
    g_stab[p * DH + n] = s;
}

// ---------------------------------------------------------------------------
// Pre-convert x and Wq/Wk/Wv to bf16 hi/lo planes.  8 floats per thread.
// ---------------------------------------------------------------------------
#define NX8 (NTOK * DM / 8)            // 1048576
#define NW8 (DH * DM / 8)              // 16384
__global__ __launch_bounds__(256) void convert_inputs(
    const float* __restrict__ x,  const float* __restrict__ Wq,
    const float* __restrict__ Wk, const float* __restrict__ Wv)
{
    size_t gid = (size_t)blockIdx.x * 256 + threadIdx.x;
    const float* src;
    unsigned short *dhi, *dlo;
    size_t e0;
    if (gid < NX8) {
        src = x; dhi = g_Xhi; dlo = g_Xlo; e0 = gid * 8;
    } else {
        size_t r = gid - NX8;
        int mat = (int)(r / NW8);
        size_t rr = r - (size_t)mat * NW8;
        src = (mat == 0) ? Wq : ((mat == 1) ? Wk : Wv);
        dhi = g_Whi + (size_t)mat * DH * DM;
        dlo = g_Wlo + (size_t)mat * DH * DM;
        e0 = rr * 8;
    }
    float4 a = *(const float4*)(src + e0);
    float4 b = *(const float4*)(src + e0 + 4);
    uint32_t hp[4], lp[4];
    split2(a.x, a.y, hp[0], lp[0]);
    split2(a.z, a.w, hp[1], lp[1]);
    split2(b.x, b.y, hp[2], lp[2]);
    split2(b.z, b.w, hp[3], lp[3]);
    *(uint4*)(dhi + e0) = make_uint4(hp[0], hp[1], hp[2], hp[3]);
    *(uint4*)(dlo + e0) = make_uint4(lp[0], lp[1], lp[2], lp[3]);
}

// ---------------------------------------------------------------------------
// QKV projection, bf16x3 mma, 2-stage cp.async pipeline, M=64 tiles.
// (R14 passing version)
// ---------------------------------------------------------------------------
#define QS 20
#define QO_XHI 0
#define QO_XLO (64 * QS)
#define QO_WHI (2 * 64 * QS)
#define QO_WLO (2 * 64 * QS + 128 * QS)
#define QSTG   (2 * 64 * QS + 2 * 128 * QS)   // 7680 u32 per stage
#define QKV_SMEM (2 * QSTG * 4)               // 61440 bytes

__global__ __launch_bounds__(256, 3)
void qkv_mma(int dummy) {
    extern __shared__ uint32_t qsm[];
    const uint32_t sbq = s2u(qsm);

    const int tid = threadIdx.x;
    const int lane = tid & 31, wid = tid >> 5;
    const int warp_m = wid & 1, warp_n = wid >> 1;     // 2m x 4n
    const int m_base = warp_m * 32, n_base = warp_n * 32;
    const int lq4 = lane >> 2, lk = lane & 3;
    const int t0 = blockIdx.x * 64;
    const int mat = blockIdx.y;

    const unsigned short* wHi = g_Whi + (size_t)mat * DH * DM;
    const unsigned short* wLo = g_Wlo + (size_t)mat * DH * DM;

    const int lrow = tid >> 2, lq = tid & 3;       // X: 64 rows x 4 quarters
    const int wrow = tid >> 1, whalf = tid & 1;    // W: 128 rows x 2 halves

    auto loadChunk = [&](int ci, int st) {
        const size_t xb = ((size_t)(t0 + lrow) * DM + ci * 32 + lq * 8) * 2;
        const size_t wb = ((size_t)wrow * DM + ci * 32 + whalf * 16) * 2;
        const uint32_t s0 = sbq + st * (QSTG * 4);
        const uint32_t dx = s0 + (lrow * QS + lq * 4) * 4;
        const uint32_t dw = s0 + (wrow * QS + whalf * 8) * 4;
        CPA16(dx + QO_XHI * 4,      (const char*)g_Xhi + xb);
        CPA16(dx + QO_XLO * 4,      (const char*)g_Xlo + xb);
        CPA16(dw + QO_WHI * 4,      (const char*)wHi + wb);
        CPA16(dw + QO_WHI * 4 + 16, (const char*)wHi + wb + 16);
        CPA16(dw + QO_WLO * 4,      (const char*)wLo + wb);
        CPA16(dw + QO_WLO * 4 + 16, (const char*)wLo + wb + 16);
    };

    float acc[2][4][4];
#pragma unroll
    for (int i = 0; i < 2; i++)
#pragma unroll
        for (int j = 0; j < 4; j++)
#pragma unroll
            for (int k = 0; k < 4; k++) acc[i][j][k] = 0.f;

    loadChunk(0, 0);
    CPA_COMMIT();

    for (int ci = 0; ci < 32; ci++) {
        if (ci + 1 < 32) {
            loadChunk(ci + 1, (ci + 1) & 1);
            CPA_COMMIT();
            CPA_WAIT1();
        } else {
            CPA_WAIT0();
        }
        __syncthreads();

        const uint32_t* st = qsm + (ci & 1) * QSTG;
#pragma unroll
        for (int kk = 0; kk < 2; kk++) {
            const int base = kk * 8 + lk;
            uint32_t ah[2][4], al[2][4];
#pragma unroll
            for (int mt = 0; mt < 2; mt++) {
                const uint32_t* ph = st + QO_XHI + (m_base + mt * 16 + lq4) * QS;
                const uint32_t* pl = st + QO_XLO + (m_base + mt * 16 + lq4) * QS;
                ah[mt][0] = ph[base];     ah[mt][1] = ph[base + 8 * QS];
                ah[mt][2] = ph[base + 4]; ah[mt][3] = ph[base + 8 * QS + 4];
                al[mt][0] = pl[base];     al[mt][1] = pl[base + 8 * QS];
                al[mt][2] = pl[base + 4]; al[mt][3] = pl[base + 8 * QS + 4];
            }
#pragma unroll
            for (int nt = 0; nt < 4; nt++) {
                const uint32_t* ph = st + QO_WHI + (n_base + nt * 8 + lq4) * QS;
                const uint32_t* pl = st + QO_WLO + (n_base + nt * 8 + lq4) * QS;
                uint32_t bh[2] = {ph[base], ph[base + 4]};
                uint32_t bl[2] = {pl[base], pl[base + 4]};
#pragma unroll
                for (int mt = 0; mt < 2; mt++) {
                    mma16(acc[mt][nt], ah[mt], bh);
                    mma16(acc[mt][nt], ah[mt], bl);
                    mma16(acc[mt][nt], al[mt], bh);
                }
            }
        }
        __syncthreads();
    }

    if (mat < 2) {
        const float sc = (mat == 0) ? (QSCALE * LOG2E) : 1.f;
        unsigned short* dhi = (mat == 0) ? g_Qhi : g_Khi;
        unsigned short* dlo = (mat == 0) ? g_Qlo : g_Klo;
#pragma unroll
        for (int mt = 0; mt < 2; mt++)
#pragma unroll
            for (int h = 0; h < 2; h++) {
                const int tok = t0 + m_base + mt * 16 + lq4 + 8 * h;
                const int pos = tok & (TSEQ - 1);
#pragma unroll
                for (int nt = 0; nt < 4; nt++) {
                    const int colE = n_base + nt * 8 + 2 * lk;
                    float e = acc[mt][nt][2 * h] * sc;
                    float o = acc[mt][nt][2 * h + 1] * sc;
                    float ct = g_ctab[pos * DH + colE];
                    float st = g_stab[pos * DH + colE];
                    float re = e * ct + o * st;
                    float ro = o * ct - e * st;
                    uint32_t hi, lo;
                    split2(re, ro, hi, lo);
                    *(uint32_t*)&dhi[(size_t)tok * DH + colE] = hi;
                    *(uint32_t*)&dlo[(size_t)tok * DH + colE] = lo;
                }
            }
    } else {
#pragma unroll
        for (int mt = 0; mt < 2; mt++)
#pragma unroll
            for (int h = 0; h < 2; h++) {
                const int tok = t0 + m_base + mt * 16 + lq4 + 8 * h;
#pragma unroll
                for (int nt = 0; nt < 4; nt++) {
                    const int colE = n_base + nt * 8 + 2 * lk;
#pragma unroll
                    for (int e = 0; e < 2; e++) {
                        float v = acc[mt][nt][2 * h + e];
                        __nv_bfloat16 hb = __float2bfloat16(v);
                        __nv_bfloat16 lb = __float2bfloat16(v - __bfloat162float(hb));
                        g_Vthi[(size_t)(colE + e) * NTOK + tok] = __bfloat16_as_ushort(hb);
                        g_Vtlo[(size_t)(colE + e) * NTOK + tok] = __bfloat16_as_ushort(lb);
                    }
                }
            }
    }
}

// ---------------------------------------------------------------------------
// Flash attention partials — FA2 register-P, ldmatrix, 2 CTAs/SM.
// 576 blocks x 128 threads (4 warps).  Block = (batch, 64-q tile, 256-key
// chunk); key tiles of 64.  Warp owns 16 q x all 64 keys.
// ---------------------------------------------------------------------------
#define AST 68                         // Q/K row stride (u32)
#define VST 36                         // V row stride (u32): 64 keys + pad
#define O_QHI 0
#define O_QLO (O_QHI + 64 * AST)
#define O_KHI (O_QLO + 64 * AST)
#define O_KLO (O_KHI + 64 * AST)
#define O_VHI (O_KLO + 64 * AST)
#define O_VLO (O_VHI + 128 * VST)
#define AT_SMEM ((O_VLO + 128 * VST) * 4)   // 106496 bytes -> 2 CTAs/SM
#define NTPK (16 * AST * 4)            // K: 16 rows stride (bytes)
#define NDPV (16 * VST * 4)            // V: 16 rows stride (bytes)

__global__ __launch_bounds__(128, 2) void attn_part(int dummy)
{
    extern __shared__ uint32_t smu[];
    const uint32_t sb = s2u(smu);

    const int tid = threadIdx.x;
    const int lane = tid & 31, wid = tid >> 5;   // 4 warps
    const int m_base = wid * 16;
    const int lq4 = lane >> 2, lk = lane & 3;

    // ldmatrix per-lane addressing
    const int a_row = m_base + (lane & 15);
    const int a_seg = lane >> 4;
    const int b_sub = (lane & 7) + ((lane >> 4) & 1) * 8;
    const int b_seg = (lane >> 3) & 1;

    const uint32_t aQh = sb + (O_QHI + a_row * AST + a_seg * 4) * 4;
    const uint32_t aQl = sb + (O_QLO + a_row * AST + a_seg * 4) * 4;
    const uint32_t aKh = sb + (O_KHI + b_sub * AST + b_seg * 4) * 4;
    const uint32_t aKl = sb + (O_KLO + b_sub * AST + b_seg * 4) * 4;
    const uint32_t aVh = sb + (O_VHI + b_sub * VST + b_seg * 4) * 4;
    const uint32_t aVl = sb + (O_VLO + b_sub * VST + b_seg * 4) * 4;

    // block -> (b, qt, chunk): qt in [0,32) of 64 q-rows; 256-key chunks;
    // nch = qt/4 + 1; per-batch blocks = 144.
    int rr = blockIdx.x % 144;
    int b  = blockIdx.x / 144;
    int qt = 0, chunk = rr;
    for (int i = 0; i < 32; i++) {
        int cnt = (i >> 2) + 1;
        if (chunk < cnt) { qt = i; break; }
        chunk -= cnt;
    }

    const int q0   = qt * 64;
    const int kbeg = chunk * 256;
    const int kend = min(q0 + 64, kbeg + 256);
    const int tokb = b * TSEQ;

    auto loadK = [&](int ks_) {
#pragma unroll
        for (int it = 0; it < 8; it++) {
            int idx = tid + 128 * it;
            int row = idx >> 4, c = idx & 15;
            CPA16(sb + (O_KHI + row * AST + c * 4) * 4,
                  (const char*)g_Khi + ((size_t)(tokb + ks_ + row) * DH + c * 8) * 2);
            CPA16(sb + (O_KLO + row * AST + c * 4) * 4,
                  (const char*)g_Klo + ((size_t)(tokb + ks_ + row) * DH + c * 8) * 2);
        }
    };
    auto loadV = [&](int ks_) {
#pragma unroll
        for (int it = 0; it < 8; it++) {
            int idx = tid + 128 * it;
            int row = idx >> 3, c = idx & 7;          // 128 d-rows x 8 key-chunks
            CPA16(sb + (O_VHI + row * VST + c * 4) * 4,
                  (const char*)g_Vthi + ((size_t)row * NTOK + tokb + ks_ + c * 8) * 2);
            CPA16(sb + (O_VLO + row * VST + c * 4) * 4,
                  (const char*)g_Vtlo + ((size_t)row * NTOK + tokb + ks_ + c * 8) * 2);
        }
    };

    // group0: Q + K0    group1: V0
#pragma unroll
    for (int it = 0; it < 8; it++) {
        int idx = tid + 128 * it;
        int row = idx >> 4, c = idx & 15;
        CPA16(sb + (O_QHI + row * AST + c * 4) * 4,
              (const char*)g_Qhi + ((size_t)(tokb + q0 + row) * DH + c * 8) * 2);
        CPA16(sb + (O_QLO + row * AST + c * 4) * 4,
              (const char*)g_Qlo + ((size_t)(tokb + q0 + row) * DH + c * 8) * 2);
    }
    loadK(kbeg);
    CPA_COMMIT();
    loadV(kbeg);
    CPA_COMMIT();

    float m_lo = -1e30f, m_hi = -1e30f, l_lo = 0.f, l_hi = 0.f;
    float o_[16][4];
#pragma unroll
    for (int j = 0; j < 16; j++)
#pragma unroll
        for (int k = 0; k < 4; k++) o_[j][k] = 0.f;

    for (int ks = kbeg; ks < kend; ks += 64) {
        const bool last = (ks + 64 >= kend);
        CPA_WAIT1();               // Q+K_cur resident; V_cur may be in flight
        __syncthreads();

        // ---- S = Q K^T : warp covers 16 rows x 64 keys ----
        float s_[8][4];
#pragma unroll
        for (int j = 0; j < 8; j++)
#pragma unroll
            for (int k = 0; k < 4; k++) s_[j][k] = 0.f;
#pragma unroll
        for (int k8 = 0; k8 < 8; k8++) {
            uint32_t ah[4], al[4];
            LDSM4(ah[0], ah[1], ah[2], ah[3], aQh + k8 * 32);
            LDSM4(al[0], al[1], al[2], al[3], aQl + k8 * 32);
#pragma unroll
            for (int ntp = 0; ntp < 4; ntp++) {
                uint32_t bh[4], bl[4];
                LDSM4(bh[0], bh[1], bh[2], bh[3], aKh + ntp * NTPK + k8 * 32);
                LDSM4(bl[0], bl[1], bl[2], bl[3], aKl + ntp * NTPK + k8 * 32);
                mma16(s_[2 * ntp],     ah, bh);
                mma16(s_[2 * ntp + 1], ah, bh + 2);
                mma16(s_[2 * ntp],     ah, bl);
                mma16(s_[2 * ntp + 1], ah, bl + 2);
                mma16(s_[2 * ntp],     al, bh);
                mma16(s_[2 * ntp + 1], al, bh + 2);
            }
        }

        // ---- causal mask (diagonal tile only) ----
        if (ks + 64 > q0) {
            const int q_lo = q0 + m_base + lq4, q_hi = q_lo + 8;
#pragma unroll
            for (int nt = 0; nt < 8; nt++) {
                const int key0 = ks + nt * 8 + 2 * lk;
                if (key0 > q_lo)     s_[nt][0] = -1e30f;
                if (key0 + 1 > q_lo) s_[nt][1] = -1e30f;
                if (key0 > q_hi)     s_[nt][2] = -1e30f;
                if (key0 + 1 > q_hi) s_[nt][3] = -1e30f;
            }
        }

        // ---- warp-local online softmax (log2 units) ----
        float mx0 = -1e30f, mx1 = -1e30f;
#pragma unroll
        for (int nt = 0; nt < 8; nt++) {
            mx0 = fmaxf(mx0, fmaxf(s_[nt][0], s_[nt][1]));
            mx1 = fmaxf(mx1, fmaxf(s_[nt][2], s_[nt][3]));
        }
        mx0 = fmaxf(mx0, __shfl_xor_sync(0xffffffffu, mx0, 1));
        mx0 = fmaxf(mx0, __shfl_xor_sync(0xffffffffu, mx0, 2));
        mx1 = fmaxf(mx1, __shfl_xor_sync(0xffffffffu, mx1, 1));
        mx1 = fmaxf(mx1, __shfl_xor_sync(0xffffffffu, mx1, 2));

        const float mn_lo = fmaxf(m_lo, mx0);
        const float mn_hi = fmaxf(m_hi, mx1);
        const float al_ = ex2f(m_lo - mn_lo);
        const float ah_ = ex2f(m_hi - mn_hi);
        m_lo = mn_lo; m_hi = mn_hi;

        // P in registers: packed bf16 hi/lo A-fragments
        float ps0 = 0.f, ps1 = 0.f;
#pragma unroll
        for (int nt = 0; nt < 8; nt++) {
            float p0 = ex2f(s_[nt][0] - mn_lo);
            float p1 = ex2f(s_[nt][1] - mn_lo);
            float p2 = ex2f(s_[nt][2] - mn_hi);
            float p3 = ex2f(s_[nt][3] - mn_hi);
            ps0 += p0 + p1;
            ps1 += p2 + p3;
            uint32_t h0, l0, h1, l1;
            split2(p0, p1, h0, l0);
            split2(p2, p3, h1, l1);
            s_[nt][0] = __uint_as_float(h0);
            s_[nt][1] = __uint_as_float(h1);
            s_[nt][2] = __uint_as_float(l0);
            s_[nt][3] = __uint_as_float(l1);
        }
        ps0 += __shfl_xor_sync(0xffffffffu, ps0, 1);
        ps0 += __shfl_xor_sync(0xffffffffu, ps0, 2);
        ps1 += __shfl_xor_sync(0xffffffffu, ps1, 1);
        ps1 += __shfl_xor_sync(0xffffffffu, ps1, 2);
        l_lo = l_lo * al_ + ps0;
        l_hi = l_hi * ah_ + ps1;
#pragma unroll
        for (int nd = 0; nd < 16; nd++) {
            o_[nd][0] *= al_; o_[nd][1] *= al_;
            o_[nd][2] *= ah_; o_[nd][3] *= ah_;
        }

        CPA_WAIT0();               // V_cur resident
        __syncthreads();           // + all warps done reading K
        if (!last) { loadK(ks + 64); CPA_COMMIT(); }

        // ---- O += P V : A from registers (hi+lo), B via ldmatrix ----
#pragma unroll
        for (int kk = 0; kk < 4; kk++) {
            uint32_t pa_h[4] = {__float_as_uint(s_[2 * kk][0]), __float_as_uint(s_[2 * kk][1]),
                                __float_as_uint(s_[2 * kk + 1][0]), __float_as_uint(s_[2 * kk + 1][1])};
            uint32_t pa_l[4] = {__float_as_uint(s_[2 * kk][2]), __float_as_uint(s_[2 * kk][3]),
                                __float_as_uint(s_[2 * kk + 1][2]), __float_as_uint(s_[2 * kk + 1][3])};
#pragma unroll
            for (int ndp = 0; ndp < 8; ndp++) {
                uint32_t bh[4], bl[4];
                LDSM4(bh[0], bh[1], bh[2], bh[3], aVh + ndp * NDPV + kk * 32);
                LDSM4(bl[0], bl[1], bl[2], bl[3], aVl + ndp * NDPV + kk * 32);
                mma16(o_[2 * ndp],     pa_h, bh);
                mma16(o_[2 * ndp + 1], pa_h, bh + 2);
                mma16(o_[2 * ndp],     pa_h, bl);
                mma16(o_[2 * ndp + 1], pa_h, bl + 2);
                mma16(o_[2 * ndp],     pa_l, bh);
                mma16(o_[2 * ndp + 1], pa_l, bh + 2);
            }
        }

        if (!last) {
            __syncthreads();       // all warps done reading V
            loadV(ks + 64);
            CPA_COMMIT();
        }
    }

    // ---- write partials ----
    const int pbase = ((b * 32 + qt) * 8 + chunk) * 64;
#pragma unroll
    for (int h = 0; h < 2; h++) {
        const int row = m_base + lq4 + 8 * h;
#pragma unroll
        for (int nd = 0; nd < 16; nd++) {
            const int col = nd * 8 + 2 * lk;
            *(float2*)&g_Op[(size_t)(pbase + row) * DH + col] =
                make_float2(o_[nd][2 * h], o_[nd][2 * h + 1]);
        }
    }
    if (lk == 0) {
        g_m[pbase + m_base + lq4]     = m_lo;
        g_l[pbase + m_base + lq4]     = l_lo;
        g_m[pbase + m_base + lq4 + 8] = m_hi;
        g_l[pbase + m_base + lq4 + 8] = l_hi;
    }
}

// ---------------------------------------------------------------------------
// Combine: grid (32 qt, 4 b, 2 rowgroups), 256 thr; thread = 16 d of one row.
// ---------------------------------------------------------------------------
__global__ __launch_bounds__(256) void attn_combine(float* __restrict__ out)
{
    const int qt = blockIdx.x, b = blockIdx.y;
    const int tid = threadIdx.x;
    const int q = blockIdx.z * 32 + (tid >> 3);     // 0..63
    const int d0 = (tid & 7) * 16;
    const int nch = (qt >> 2) + 1;                  // 1..8
    const int base = (b * 32 + qt) * 8 * 64 + q;    // chunk stride = 64

    float M = -1e30f;
    for (int c = 0; c < nch; c++) M = fmaxf(M, g_m[base + c * 64]);
    float L = 0.f;
    for (int c = 0; c < nch; c++)
        L += ex2f(g_m[base + c * 64] - M) * g_l[base + c * 64];
    const float inv = 1.f / L;

    float4 a0 = make_float4(0.f, 0.f, 0.f, 0.f);
    float4 a1 = make_float4(0.f, 0.f, 0.f, 0.f);
    float4 a2 = make_float4(0.f, 0.f, 0.f, 0.f);
    float4 a3 = make_float4(0.f, 0.f, 0.f, 0.f);
    for (int c = 0; c < nch; c++) {
        const float w = ex2f(g_m[base + c * 64] - M);
        const float* p = g_Op + (size_t)(base + c * 64) * DH + d0;
        float4 v0 = *(const float4*)(p);
        float4 v1 = *(const float4*)(p + 4);
        float4 v2 = *(const float4*)(p + 8);
        float4 v3 = *(const float4*)(p + 12);
        a0.x += w * v0.x; a0.y += w * v0.y; a0.z += w * v0.z; a0.w += w * v0.w;
        a1.x += w * v1.x; a1.y += w * v1.y; a1.z += w * v1.z; a1.w += w * v1.w;
        a2.x += w * v2.x; a2.y += w * v2.y; a2.z += w * v2.z; a2.w += w * v2.w;
        a3.x += w * v3.x; a3.y += w * v3.y; a3.z += w * v3.z; a3.w += w * v3.w;
    }
    a0.x *= inv; a0.y *= inv; a0.z *= inv; a0.w *= inv;
    a1.x *= inv; a1.y *= inv; a1.z *= inv; a1.w *= inv;
    a2.x *= inv; a2.y *= inv; a2.z *= inv; a2.w *= inv;
    a3.x *= inv; a3.y *= inv; a3.z *= inv; a3.w *= inv;

    float* op = out + (size_t)(b * TSEQ + qt * 64 + q) * DH + d0;
    *(float4*)(op)      = a0;
    *(float4*)(op + 4)  = a1;
    *(float4*)(op + 8)  = a2;
    *(float4*)(op + 12) = a3;
}

// ---------------------------------------------------------------------------
extern "C" void kernel_launch(void* const* d_in, const int* in_sizes, int n_in,
                              void* d_out, int out_size)
{
    const float* x     = (const float*)d_in[0];
    const float* Wq    = (const float*)d_in[1];
    const float* Wk    = (const float*)d_in[2];
    const float* Wv    = (const float*)d_in[3];
    const float* theta = (const float*)d_in[4];
    float* out = (float*)d_out;

    cudaFuncSetAttribute(qkv_mma, cudaFuncAttributeMaxDynamicSharedMemorySize, QKV_SMEM);
    cudaFuncSetAttribute(attn_part, cudaFuncAttributeMaxDynamicSharedMemorySize, AT_SMEM);

    rope_table<<<TSEQ, 128>>>(theta);
    convert_inputs<<<(NX8 + 3 * NW8) / 256, 256>>>(x, Wq, Wk, Wv);

    dim3 g1(NTOK / 64, 3);
    qkv_mma<<<g1, 256, QKV_SMEM>>>(0);

    attn_part<<<576, 128, AT_SMEM>>>(0);

    dim3 g3(32, 4, 2);
    attn_combine<<<g3, 256>>>(out);
}

// round 17
// speedup vs baseline: 1.0302x; 1.0302x over previous
#include <cuda_runtime.h>
#include <cuda_bf16.h>
#include <math.h>
#include <stdint.h>

#define TSEQ   2048
#define NTOK   8192
#define DM     1024
#define DH     128
#define QSCALE 0.03125f                 // 1/sqrt(1024)
#define LOG2E  1.4426950408889634f

// bf16 hi/lo planes of inputs (pre-converted once per launch)
__device__ unsigned short g_Xhi[NTOK * DM], g_Xlo[NTOK * DM];
__device__ unsigned short g_Whi[3 * DH * DM], g_Wlo[3 * DH * DM];
// Q,K token-major bf16 hi/lo planes; Vt transposed [DH][NTOK] planes.
__device__ unsigned short g_Qhi[NTOK * DH], g_Qlo[NTOK * DH];
__device__ unsigned short g_Khi[NTOK * DH], g_Klo[NTOK * DH];
__device__ unsigned short g_Vthi[DH * NTOK], g_Vtlo[DH * NTOK];
__device__ float g_ctab[TSEQ * DH];
__device__ float g_stab[TSEQ * DH];
// split-K partials: [b][qt16][chunk8][128 q][128 d]; m/l in log2 units
__device__ float g_Op[4 * 16 * 8 * 128 * DH];
__device__ float g_m [4 * 16 * 8 * 128];
__device__ float g_l [4 * 16 * 8 * 128];

__device__ __forceinline__ float ex2f(float x) {
    float y; asm("ex2.approx.ftz.f32 %0, %1;" : "=f"(y) : "f"(x)); return y;
}
__device__ __forceinline__ uint32_t s2u(const void* p) {
    uint32_t a;
    asm("{ .reg .u64 t; cvta.to.shared.u64 t, %1; cvt.u32.u64 %0, t; }"
        : "=r"(a) : "l"(p));
    return a;
}
#define CPA16(dst, src) \
    asm volatile("cp.async.cg.shared.global [%0], [%1], 16;" :: "r"(dst), "l"(src) : "memory")
#define CPA_COMMIT() asm volatile("cp.async.commit_group;" ::: "memory")
#define CPA_WAIT0()  asm volatile("cp.async.wait_group 0;" ::: "memory")
#define CPA_WAIT1()  asm volatile("cp.async.wait_group 1;" ::: "memory")

#define LDSM4(r0, r1, r2, r3, addr) \
    asm volatile("ldmatrix.sync.aligned.m8n8.x4.shared.b16 {%0,%1,%2,%3}, [%4];" \
        : "=r"(r0), "=r"(r1), "=r"(r2), "=r"(r3) : "r"(addr))

// bf16 m16n8k16 HMMA
__device__ __forceinline__ void mma16(float* c, const uint32_t* a, const uint32_t* b) {
    asm volatile(
        "mma.sync.aligned.m16n8k16.row.col.f32.bf16.bf16.f32 "
        "{%0,%1,%2,%3}, {%4,%5,%6,%7}, {%8,%9}, {%0,%1,%2,%3};"
        : "+f"(c[0]), "+f"(c[1]), "+f"(c[2]), "+f"(c[3])
        : "r"(a[0]), "r"(a[1]), "r"(a[2]), "r"(a[3]), "r"(b[0]), "r"(b[1]));
}

__device__ __forceinline__ void split2(float f0, float f1, uint32_t& hi, uint32_t& lo) {
    __nv_bfloat16 h0 = __float2bfloat16(f0);
    __nv_bfloat16 h1 = __float2bfloat16(f1);
    __nv_bfloat16 l0 = __float2bfloat16(f0 - __bfloat162float(h0));
    __nv_bfloat16 l1 = __float2bfloat16(f1 - __bfloat162float(h1));
    hi = (uint32_t)__bfloat16_as_ushort(h0) | ((uint32_t)__bfloat16_as_ushort(h1) << 16);
    lo = (uint32_t)__bfloat16_as_ushort(l0) | ((uint32_t)__bfloat16_as_ushort(l1) << 16);
}

// ---------------------------------------------------------------------------
__global__ __launch_bounds__(128) void rope_table(const float* __restrict__ theta) {
    int p = blockIdx.x, n = threadIdx.x;
    float s, c;
    sincosf((float)(p + 1) * theta[n], &s, &c);
    g_ctab[p * DH + n] = c;
    g_stab[p * DH + n] = s;
}

// ---------------------------------------------------------------------------
// Pre-convert x and Wq/Wk/Wv to bf16 hi/lo planes.  8 floats per thread.
// ---------------------------------------------------------------------------
#define NX8 (NTOK * DM / 8)            // 1048576
#define NW8 (DH * DM / 8)              // 16384
__global__ __launch_bounds__(256) void convert_inputs(
    const float* __restrict__ x,  const float* __restrict__ Wq,
    const float* __restrict__ Wk, const float* __restrict__ Wv)
{
    size_t gid = (size_t)blockIdx.x * 256 + threadIdx.x;
    const float* src;
    unsigned short *dhi, *dlo;
    size_t e0;
    if (gid < NX8) {
        src = x; dhi = g_Xhi; dlo = g_Xlo; e0 = gid * 8;
    } else {
        size_t r = gid - NX8;
        int mat = (int)(r / NW8);
        size_t rr = r - (size_t)mat * NW8;
        src = (mat == 0) ? Wq : ((mat == 1) ? Wk : Wv);
        dhi = g_Whi + (size_t)mat * DH * DM;
        dlo = g_Wlo + (size_t)mat * DH * DM;
        e0 = rr * 8;
    }
    float4 a = *(const float4*)(src + e0);
    float4 b = *(const float4*)(src + e0 + 4);
    uint32_t hp[4], lp[4];
    split2(a.x, a.y, hp[0], lp[0]);
    split2(a.z, a.w, hp[1], lp[1]);
    split2(b.x, b.y, hp[2], lp[2]);
    split2(b.z, b.w, hp[3], lp[3]);
    *(uint4*)(dhi + e0) = make_uint4(hp[0], hp[1], hp[2], hp[3]);
    *(uint4*)(dlo + e0) = make_uint4(lp[0], lp[1], lp[2], lp[3]);
}

// ---------------------------------------------------------------------------
// QKV projection, bf16x3 mma, 2-stage cp.async pipeline, M=64 tiles,
// ldmatrix fragment loads.  grid (128 tiles, 3 mats), 256 thr (2m x 4n).
// ---------------------------------------------------------------------------
#define QS 20
#define QO_XHI 0
#define QO_XLO (64 * QS)
#define QO_WHI (2 * 64 * QS)
#define QO_WLO (2 * 64 * QS + 128 * QS)
#define QSTG   (2 * 64 * QS + 2 * 128 * QS)   // 7680 u32 per stage
#define QKV_SMEM (2 * QSTG * 4)               // 61440 bytes

__global__ __launch_bounds__(256, 3)
void qkv_mma(int dummy) {
    extern __shared__ uint32_t qsm[];
    const uint32_t sbq = s2u(qsm);

    const int tid = threadIdx.x;
    const int lane = tid & 31, wid = tid >> 5;
    const int warp_m = wid & 1, warp_n = wid >> 1;     // 2m x 4n
    const int m_base = warp_m * 32, n_base = warp_n * 32;
    const int lq4 = lane >> 2, lk = lane & 3;
    const int t0 = blockIdx.x * 64;
    const int mat = blockIdx.y;

    const unsigned short* wHi = g_Whi + (size_t)mat * DH * DM;
    const unsigned short* wLo = g_Wlo + (size_t)mat * DH * DM;

    // ldmatrix lane addressing (same mappings as validated attn kernel)
    const int a_row0 = m_base + (lane & 15);           // rows for A frags
    const int a_off  = (lane >> 4) * 16;               // k-segment bytes
    const int b_sub  = (lane & 7) + ((lane >> 4) & 1) * 8;
    const int b_off  = ((lane >> 3) & 1) * 16;

    // base addresses (stage 0); add st*QSTG*4 per chunk
    const uint32_t aXh0 = sbq + (QO_XHI + a_row0 * QS) * 4 + a_off;
    const uint32_t aXh1 = aXh0 + 16 * QS * 4;          // mt=1 (+16 rows)
    const uint32_t aXl0 = sbq + (QO_XLO + a_row0 * QS) * 4 + a_off;
    const uint32_t aXl1 = aXl0 + 16 * QS * 4;
    const uint32_t aWh0 = sbq + (QO_WHI + (n_base + b_sub) * QS) * 4 + b_off;
    const uint32_t aWh1 = aWh0 + 16 * QS * 4;          // ntp=1 (+16 rows)
    const uint32_t aWl0 = sbq + (QO_WLO + (n_base + b_sub) * QS) * 4 + b_off;
    const uint32_t aWl1 = aWl0 + 16 * QS * 4;

    const int lrow = tid >> 2, lq = tid & 3;       // X: 64 rows x 4 quarters
    const int wrow = tid >> 1, whalf = tid & 1;    // W: 128 rows x 2 halves

    auto loadChunk = [&](int ci, int st) {
        const size_t xb = ((size_t)(t0 + lrow) * DM + ci * 32 + lq * 8) * 2;
        const size_t wb = ((size_t)wrow * DM + ci * 32 + whalf * 16) * 2;
        const uint32_t s0 = sbq + st * (QSTG * 4);
        const uint32_t dx = s0 + (lrow * QS + lq * 4) * 4;
        const uint32_t dw = s0 + (wrow * QS + whalf * 8) * 4;
        CPA16(dx + QO_XHI * 4,      (const char*)g_Xhi + xb);
        CPA16(dx + QO_XLO * 4,      (const char*)g_Xlo + xb);
        CPA16(dw + QO_WHI * 4,      (const char*)wHi + wb);
        CPA16(dw + QO_WHI * 4 + 16, (const char*)wHi + wb + 16);
        CPA16(dw + QO_WLO * 4,      (const char*)wLo + wb);
        CPA16(dw + QO_WLO * 4 + 16, (const char*)wLo + wb + 16);
    };

    float acc[2][4][4];
#pragma unroll
    for (int i = 0; i < 2; i++)
#pragma unroll
        for (int j = 0; j < 4; j++)
#pragma unroll
            for (int k = 0; k < 4; k++) acc[i][j][k] = 0.f;

    loadChunk(0, 0);
    CPA_COMMIT();

    for (int ci = 0; ci < 32; ci++) {
        if (ci + 1 < 32) {
            loadChunk(ci + 1, (ci + 1) & 1);
            CPA_COMMIT();
            CPA_WAIT1();
        } else {
            CPA_WAIT0();
        }
        __syncthreads();

        const uint32_t stoff = (ci & 1) * (QSTG * 4);
#pragma unroll
        for (int kk = 0; kk < 2; kk++) {
            const uint32_t ko = stoff + kk * 32;
            uint32_t ah[2][4], al[2][4];
            LDSM4(ah[0][0], ah[0][1], ah[0][2], ah[0][3], aXh0 + ko);
            LDSM4(ah[1][0], ah[1][1], ah[1][2], ah[1][3], aXh1 + ko);
            LDSM4(al[0][0], al[0][1], al[0][2], al[0][3], aXl0 + ko);
            LDSM4(al[1][0], al[1][1], al[1][2], al[1][3], aXl1 + ko);
#pragma unroll
            for (int ntp = 0; ntp < 2; ntp++) {
                uint32_t bh[4], bl[4];
                LDSM4(bh[0], bh[1], bh[2], bh[3], (ntp ? aWh1 : aWh0) + ko);
                LDSM4(bl[0], bl[1], bl[2], bl[3], (ntp ? aWl1 : aWl0) + ko);
#pragma unroll
                for (int mt = 0; mt < 2; mt++) {
                    // per-accumulator order hh -> hl -> lh (bitwise identical)
                    mma16(acc[mt][2 * ntp],     ah[mt], bh);
                    mma16(acc[mt][2 * ntp],     ah[mt], bl);
                    mma16(acc[mt][2 * ntp],     al[mt], bh);
                    mma16(acc[mt][2 * ntp + 1], ah[mt], bh + 2);
                    mma16(acc[mt][2 * ntp + 1], ah[mt], bl + 2);
                    mma16(acc[mt][2 * ntp + 1], al[mt], bh + 2);
                }
            }
        }
        __syncthreads();
    }

    if (mat < 2) {
        const float sc = (mat == 0) ? (QSCALE * LOG2E) : 1.f;
        unsigned short* dhi = (mat == 0) ? g_Qhi : g_Khi;
        unsigned short* dlo = (mat == 0) ? g_Qlo : g_Klo;
#pragma unroll
        for (int mt = 0; mt < 2; mt++)
#pragma unroll
            for (int h = 0; h < 2; h++) {
                const int tok = t0 + m_base + mt * 16 + lq4 + 8 * h;
                const int pos = tok & (TSEQ - 1);
#pragma unroll
                for (int nt = 0; nt < 4; nt++) {
                    const int colE = n_base + nt * 8 + 2 * lk;
                    float e = acc[mt][nt][2 * h] * sc;
                    float o = acc[mt][nt][2 * h + 1] * sc;
                    float ct = g_ctab[pos * DH + colE];
                    float st = g_stab[pos * DH + colE];
                    float re = e * ct + o * st;
                    float ro = o * ct - e * st;
                    uint32_t hi, lo;
                    split2(re, ro, hi, lo);
                    *(uint32_t*)&dhi[(size_t)tok * DH + colE] = hi;
                    *(uint32_t*)&dlo[(size_t)tok * DH + colE] = lo;
                }
            }
    } else {
#pragma unroll
        for (int mt = 0; mt < 2; mt++)
#pragma unroll
            for (int h = 0; h < 2; h++) {
                const int tok = t0 + m_base + mt * 16 + lq4 + 8 * h;
#pragma unroll
                for (int nt = 0; nt < 4; nt++) {
                    const int colE = n_base + nt * 8 + 2 * lk;
#pragma unroll
                    for (int e = 0; e < 2; e++) {
                        float v = acc[mt][nt][2 * h + e];
                        __nv_bfloat16 hb = __float2bfloat16(v);
                        __nv_bfloat16 lb = __float2bfloat16(v - __bfloat162float(hb));
                        g_Vthi[(size_t)(colE + e) * NTOK + tok] = __bfloat16_as_ushort(hb);
                        g_Vtlo[(size_t)(colE + e) * NTOK + tok] = __bfloat16_as_ushort(lb);
                    }
                }
            }
    }
}

// ---------------------------------------------------------------------------
// Flash attention partials — R14 best-known config (FA2 register-P, ldmatrix).
// 288 blocks x 256 threads (8 warps).
// ---------------------------------------------------------------------------
#define AST 68
#define O_QHI 0
#define O_QLO (O_QHI + 128 * AST)
#define O_KHI (O_QLO + 128 * AST)
#define O_KLO (O_KHI + 128 * AST)
#define O_VHI (O_KLO + 128 * AST)
#define O_VLO (O_VHI + 128 * AST)
#define AT_SMEM ((O_VLO + 128 * AST) * 4)    // 208896 bytes

__global__ __launch_bounds__(256, 1) void attn_part(int dummy)
{
    extern __shared__ uint32_t smu[];
    const uint32_t sb = s2u(smu);

    const int tid = threadIdx.x;
    const int lane = tid & 31, wid = tid >> 5;   // 8 warps
    const int m_base = wid * 16;
    const int lq4 = lane >> 2, lk = lane & 3;

    const int a_row = m_base + (lane & 15);
    const int a_seg = lane >> 4;
    const int b_sub = (lane & 7) + ((lane >> 4) & 1) * 8;
    const int b_seg = (lane >> 3) & 1;

    const uint32_t aQh = sb + (O_QHI + a_row * AST + a_seg * 4) * 4;
    const uint32_t aQl = sb + (O_QLO + a_row * AST + a_seg * 4) * 4;
    const uint32_t aKh = sb + (O_KHI + b_sub * AST + b_seg * 4) * 4;
    const uint32_t aKl = sb + (O_KLO + b_sub * AST + b_seg * 4) * 4;
    const uint32_t aVh = sb + (O_VHI + b_sub * AST + b_seg * 4) * 4;
    const uint32_t aVl = sb + (O_VLO + b_sub * AST + b_seg * 4) * 4;
#define NTP_STRIDE (16 * AST * 4)

    int rr = blockIdx.x % 72;
    int b  = blockIdx.x / 72;
    int qt = 0, chunk = rr;
    for (int i = 0; i < 16; i++) {
        int cnt = (i + 2) >> 1;
        if (chunk < cnt) { qt = i; break; }
        chunk -= cnt;
    }

    const int q0   = qt * 128;
    const int kbeg = chunk * 256;
    const int kend = min(q0 + 128, kbeg + 256);
    const int tokb = b * TSEQ;

    auto loadK = [&](int ks_) {
#pragma unroll
        for (int it = 0; it < 8; it++) {
            int idx = tid + 256 * it;
            int row = idx >> 4, c = idx & 15;
            CPA16(sb + (O_KHI + row * AST + c * 4) * 4,
                  (const char*)g_Khi + ((size_t)(tokb + ks_ + row) * DH + c * 8) * 2);
            CPA16(sb + (O_KLO + row * AST + c * 4) * 4,
                  (const char*)g_Klo + ((size_t)(tokb + ks_ + row) * DH + c * 8) * 2);
        }
    };
    auto loadV = [&](int ks_) {
#pragma unroll
        for (int it = 0; it < 8; it++) {
            int idx = tid + 256 * it;
            int row = idx >> 4, c = idx & 15;
            CPA16(sb + (O_VHI + row * AST + c * 4) * 4,
                  (const char*)g_Vthi + ((size_t)row * NTOK + tokb + ks_ + c * 8) * 2);
            CPA16(sb + (O_VLO + row * AST + c * 4) * 4,
                  (const char*)g_Vtlo + ((size_t)row * NTOK + tokb + ks_ + c * 8) * 2);
        }
    };

#pragma unroll
    for (int it = 0; it < 8; it++) {
        int idx = tid + 256 * it;
        int row = idx >> 4, c = idx & 15;
        CPA16(sb + (O_QHI + row * AST + c * 4) * 4,
              (const char*)g_Qhi + ((size_t)(tokb + q0 + row) * DH + c * 8) * 2);
        CPA16(sb + (O_QLO + row * AST + c * 4) * 4,
              (const char*)g_Qlo + ((size_t)(tokb + q0 + row) * DH + c * 8) * 2);
    }
    loadK(kbeg);
    CPA_COMMIT();
    loadV(kbeg);
    CPA_COMMIT();

    float m_lo = -1e30f, m_hi = -1e30f, l_lo = 0.f, l_hi = 0.f;
    float o_[16][4];
#pragma unroll
    for (int j = 0; j < 16; j++)
#pragma unroll
        for (int k = 0; k < 4; k++) o_[j][k] = 0.f;

    for (int ks = kbeg; ks < kend; ks += 128) {
        const bool last = (ks + 128 >= kend);
        CPA_WAIT1();
        __syncthreads();

        float s_[16][4];
#pragma unroll
        for (int j = 0; j < 16; j++)
#pragma unroll
            for (int k = 0; k < 4; k++) s_[j][k] = 0.f;
#pragma unroll
        for (int k8 = 0; k8 < 8; k8++) {
            uint32_t ah[4], al[4];
            LDSM4(ah[0], ah[1], ah[2], ah[3], aQh + k8 * 32);
            LDSM4(al[0], al[1], al[2], al[3], aQl + k8 * 32);
#pragma unroll
            for (int ntp = 0; ntp < 8; ntp++) {
                uint32_t bh[4], bl[4];
                LDSM4(bh[0], bh[1], bh[2], bh[3], aKh + ntp * NTP_STRIDE + k8 * 32);
                LDSM4(bl[0], bl[1], bl[2], bl[3], aKl + ntp * NTP_STRIDE + k8 * 32);
                mma16(s_[2 * ntp],     ah, bh);
                mma16(s_[2 * ntp],     ah, bl);
                mma16(s_[2 * ntp],     al, bh);
                mma16(s_[2 * ntp + 1], ah, bh + 2);
                mma16(s_[2 * ntp + 1], ah, bl + 2);
                mma16(s_[2 * ntp + 1], al, bh + 2);
            }
        }

        if (ks + 128 > q0) {
            const int q_lo = q0 + m_base + lq4, q_hi = q_lo + 8;
#pragma unroll
            for (int nt = 0; nt < 16; nt++) {
                const int key0 = ks + nt * 8 + 2 * lk;
                if (key0 > q_lo)     s_[nt][0] = -1e30f;
                if (key0 + 1 > q_lo) s_[nt][1] = -1e30f;
                if (key0 > q_hi)     s_[nt][2] = -1e30f;
                if (key0 + 1 > q_hi) s_[nt][3] = -1e30f;
            }
        }

        float mx0 = -1e30f, mx1 = -1e30f;
#pragma unroll
        for (int nt = 0; nt < 16; nt++) {
            mx0 = fmaxf(mx0, fmaxf(s_[nt][0], s_[nt][1]));
            mx1 = fmaxf(mx1, fmaxf(s_[nt][2], s_[nt][3]));
        }
        mx0 = fmaxf(mx0, __shfl_xor_sync(0xffffffffu, mx0, 1));
        mx0 = fmaxf(mx0, __shfl_xor_sync(0xffffffffu, mx0, 2));
        mx1 = fmaxf(mx1, __shfl_xor_sync(0xffffffffu, mx1, 1));
        mx1 = fmaxf(mx1, __shfl_xor_sync(0xffffffffu, mx1, 2));

        const float mn_lo = fmaxf(m_lo, mx0);
        const float mn_hi = fmaxf(m_hi, mx1);
        const float al_ = ex2f(m_lo - mn_lo);
        const float ah_ = ex2f(m_hi - mn_hi);
        m_lo = mn_lo; m_hi = mn_hi;

        float ps0 = 0.f, ps1 = 0.f;
#pragma unroll
        for (int nt = 0; nt < 16; nt++) {
            float p0 = ex2f(s_[nt][0] - mn_lo);
            float p1 = ex2f(s_[nt][1] - mn_lo);
            float p2 = ex2f(s_[nt][2] - mn_hi);
            float p3 = ex2f(s_[nt][3] - mn_hi);
            ps0 += p0 + p1;
            ps1 += p2 + p3;
            uint32_t h0, l0, h1, l1;
            split2(p0, p1, h0, l0);
            split2(p2, p3, h1, l1);
            s_[nt][0] = __uint_as_float(h0);
            s_[nt][1] = __uint_as_float(h1);
            s_[nt][2] = __uint_as_float(l0);
            s_[nt][3] = __uint_as_float(l1);
        }
        ps0 += __shfl_xor_sync(0xffffffffu, ps0, 1);
        ps0 += __shfl_xor_sync(0xffffffffu, ps0, 2);
        ps1 += __shfl_xor_sync(0xffffffffu, ps1, 1);
        ps1 += __shfl_xor_sync(0xffffffffu, ps1, 2);
        l_lo = l_lo * al_ + ps0;
        l_hi = l_hi * ah_ + ps1;
#pragma unroll
        for (int nd = 0; nd < 16; nd++) {
            o_[nd][0] *= al_; o_[nd][1] *= al_;
            o_[nd][2] *= ah_; o_[nd][3] *= ah_;
        }

        CPA_WAIT0();
        __syncthreads();
        if (!last) { loadK(ks + 128); CPA_COMMIT(); }

#pragma unroll
        for (int kk = 0; kk < 8; kk++) {
            uint32_t pa_h[4] = {__float_as_uint(s_[2 * kk][0]), __float_as_uint(s_[2 * kk][1]),
                                __float_as_uint(s_[2 * kk + 1][0]), __float_as_uint(s_[2 * kk + 1][1])};
            uint32_t pa_l[4] = {__float_as_uint(s_[2 * kk][2]), __float_as_uint(s_[2 * kk][3]),
                                __float_as_uint(s_[2 * kk + 1][2]), __float_as_uint(s_[2 * kk + 1][3])};
#pragma unroll
            for (int ndp = 0; ndp < 8; ndp++) {
                uint32_t bh[4], bl[4];
                LDSM4(bh[0], bh[1], bh[2], bh[3], aVh + ndp * NTP_STRIDE + kk * 32);
                LDSM4(bl[0], bl[1], bl[2], bl[3], aVl + ndp * NTP_STRIDE + kk * 32);
                mma16(o_[2 * ndp],     pa_h, bh);
                mma16(o_[2 * ndp],     pa_h, bl);
                mma16(o_[2 * ndp],     pa_l, bh);
                mma16(o_[2 * ndp + 1], pa_h, bh + 2);
                mma16(o_[2 * ndp + 1], pa_h, bl + 2);
                mma16(o_[2 * ndp + 1], pa_l, bh + 2);
            }
        }

        if (!last) {
            __syncthreads();
            loadV(ks + 128);
            CPA_COMMIT();
        }
    }

    const int pbase = ((b * 16 + qt) * 8 + chunk) * 128;
#pragma unroll
    for (int h = 0; h < 2; h++) {
        const int row = m_base + lq4 + 8 * h;
#pragma unroll
        for (int nd = 0; nd < 16; nd++) {
            const int col = nd * 8 + 2 * lk;
            *(float2*)&g_Op[(size_t)(pbase + row) * DH + col] =
                make_float2(o_[nd][2 * h], o_[nd][2 * h + 1]);
        }
    }
    if (lk == 0) {
        g_m[pbase + m_base + lq4]     = m_lo;
        g_l[pbase + m_base + lq4]     = l_lo;
        g_m[pbase + m_base + lq4 + 8] = m_hi;
        g_l[pbase + m_base + lq4 + 8] = l_hi;
    }
}

// ---------------------------------------------------------------------------
// Combine: grid (16 qt, 4 b, 4 rowgroups), 256 thr.
// ---------------------------------------------------------------------------
__global__ __launch_bounds__(256) void attn_combine(float* __restrict__ out)
{
    const int qt = blockIdx.x, b = blockIdx.y;
    const int tid = threadIdx.x;
    const int q = blockIdx.z * 32 + (tid >> 3);
    const int d0 = (tid & 7) * 16;
    const int nch = (qt + 2) >> 1;
    const int base = (b * 16 + qt) * 8 * 128 + q;

    float M = -1e30f;
    for (int c = 0; c < nch; c++) M = fmaxf(M, g_m[base + c * 128]);
    float L = 0.f;
    for (int c = 0; c < nch; c++)
        L += ex2f(g_m[base + c * 128] - M) * g_l[base + c * 128];
    const float inv = 1.f / L;

    float4 a0 = make_float4(0.f, 0.f, 0.f, 0.f);
    float4 a1 = make_float4(0.f, 0.f, 0.f, 0.f);
    float4 a2 = make_float4(0.f, 0.f, 0.f, 0.f);
    float4 a3 = make_float4(0.f, 0.f, 0.f, 0.f);
    for (int c = 0; c < nch; c++) {
        const float w = ex2f(g_m[base + c * 128] - M);
        const float* p = g_Op + (size_t)(base + c * 128) * DH + d0;
        float4 v0 = *(const float4*)(p);
        float4 v1 = *(const float4*)(p + 4);
        float4 v2 = *(const float4*)(p + 8);
        float4 v3 = *(const float4*)(p + 12);
        a0.x += w * v0.x; a0.y += w * v0.y; a0.z += w * v0.z; a0.w += w * v0.w;
        a1.x += w * v1.x; a1.y += w * v1.y; a1.z += w * v1.z; a1.w += w * v1.w;
        a2.x += w * v2.x; a2.y += w * v2.y; a2.z += w * v2.z; a2.w += w * v2.w;
        a3.x += w * v3.x; a3.y += w * v3.y; a3.z += w * v3.z; a3.w += w * v3.w;
    }
    a0.x *= inv; a0.y *= inv; a0.z *= inv; a0.w *= inv;
    a1.x *= inv; a1.y *= inv; a1.z *= inv; a1.w *= inv;
    a2.x *= inv; a2.y *= inv; a2.z *= inv; a2.w *= inv;
    a3.x *= inv; a3.y *= inv; a3.z *= inv; a3.w *= inv;

    float* op = out + (size_t)(b * TSEQ + qt * 128 + q) * DH + d0;
    *(float4*)(op)      = a0;
    *(float4*)(op + 4)  = a1;
    *(float4*)(op + 8)  = a2;
    *(float4*)(op + 12) = a3;
}

// ---------------------------------------------------------------------------
extern "C" void kernel_launch(void* const* d_in, const int* in_sizes, int n_in,
                              void* d_out, int out_size)
{
    const float* x     = (const float*)d_in[0];
    const float* Wq    = (const float*)d_in[1];
    const float* Wk    = (const float*)d_in[2];
    const float* Wv    = (const float*)d_in[3];
    const float* theta = (const float*)d_in[4];
    float* out = (float*)d_out;

    cudaFuncSetAttribute(qkv_mma, cudaFuncAttributeMaxDynamicSharedMemorySize, QKV_SMEM);
    cudaFuncSetAttribute(attn_part, cudaFuncAttributeMaxDynamicSharedMemorySize, AT_SMEM);

    rope_table<<<TSEQ, 128>>>(theta);
    convert_inputs<<<(NX8 + 3 * NW8) / 256, 256>>>(x, Wq, Wk, Wv);

    dim3 g1(NTOK / 64, 3);
    qkv_mma<<<g1, 256, QKV_SMEM>>>(0);

    attn_part<<<288, 256, AT_SMEM>>>(0);

    dim3 g3(16, 4, 4);
    attn_combine<<<g3, 256>>>(out);
}